// round 11
// baseline (speedup 1.0000x reference)
#include <cuda_runtime.h>

#define B 8
#define M 8192
#define N 8192
#define SPLITS 32
#define ROWS (M / SPLITS)            // 256 rows per split
#define TPB 128
#define COLS_PER_BLOCK (TPB * 2)     // 256 columns per block (2 floats per thread)
#define NBLK (N / COLS_PER_BLOCK)    // 32 -> grid 32x32 = 1024 blocks

// Split-K partial sums: [SPLITS][B][N] floats = 8 MB device scratch.
__device__ float g_part[(size_t)SPLITS * B * N];

// Packed fp32x2 FMA: d = a*b + d  (sm_103a FFMA2, only reachable via PTX)
#define FMA2(d, a, b) \
    asm("fma.rn.f32x2 %0, %1, %2, %0;" : "+l"(d) : "l"(a), "l"(b))

__global__ void __launch_bounds__(TPB, 7)
snn_gemv_split(const float* __restrict__ pre,   // [B][M]
               const float* __restrict__ W)     // [M][N] row-major
{
    // Pre-spikes pre-duplicated: pre_s2[r][b] = {p, p} (64-bit), so packed
    // multipliers come straight from LDS.128. 256*8*8 = 16 KB smem.
    __shared__ unsigned long long pre_s2[ROWS][B];

    const int nb  = blockIdx.x;
    const int s   = blockIdx.y;
    const int tid = threadIdx.x;
    const int m0  = s * ROWS;

    #pragma unroll
    for (int r = tid; r < ROWS; r += TPB) {
        #pragma unroll
        for (int b = 0; b < B; b++) {
            float p = pre[b * M + m0 + r];
            float2 pp = make_float2(p, p);
            pre_s2[r][b] = *reinterpret_cast<unsigned long long*>(&pp);
        }
    }
    __syncthreads();

    const int n0 = nb * COLS_PER_BLOCK + tid * 2;   // 2 columns per thread
    const unsigned long long* Wp =
        reinterpret_cast<const unsigned long long*>(W + (size_t)m0 * N + n0);
    const size_t S8 = N / 2;         // row stride in 8-byte (ulonglong) units

    // acc[b] = packed pair for this thread's 2 columns
    unsigned long long acc[B];
    #pragma unroll
    for (int b = 0; b < B; b++) acc[b] = 0ull;

    // One row: 8 packed FMAs against the broadcast pre-spike pairs.
    #define DO_ROW(WV, MI) do {                                              \
        const ulonglong2* ps =                                               \
            reinterpret_cast<const ulonglong2*>(&pre_s2[(MI)][0]);           \
        ulonglong2 pa = ps[0];  /* batches 0,1 */                            \
        ulonglong2 pb = ps[1];  /* batches 2,3 */                            \
        ulonglong2 pc = ps[2];  /* batches 4,5 */                            \
        ulonglong2 pd = ps[3];  /* batches 6,7 */                            \
        FMA2(acc[0], (WV), pa.x); FMA2(acc[1], (WV), pa.y);                  \
        FMA2(acc[2], (WV), pb.x); FMA2(acc[3], (WV), pb.y);                  \
        FMA2(acc[4], (WV), pc.x); FMA2(acc[5], (WV), pc.y);                  \
        FMA2(acc[6], (WV), pd.x); FMA2(acc[7], (WV), pd.y);                  \
    } while (0)

    // 8-deep explicit load batching (8 x LDG.64 = 64 B in flight per thread,
    // same as the proven 4 x LDG.128), .CS so W streams through L2.
    #pragma unroll 1
    for (int m = 0; m < ROWS; m += 8) {
        unsigned long long w0 = __ldcs(Wp + (size_t)(m + 0) * S8);
        unsigned long long w1 = __ldcs(Wp + (size_t)(m + 1) * S8);
        unsigned long long w2 = __ldcs(Wp + (size_t)(m + 2) * S8);
        unsigned long long w3 = __ldcs(Wp + (size_t)(m + 3) * S8);
        unsigned long long w4 = __ldcs(Wp + (size_t)(m + 4) * S8);
        unsigned long long w5 = __ldcs(Wp + (size_t)(m + 5) * S8);
        unsigned long long w6 = __ldcs(Wp + (size_t)(m + 6) * S8);
        unsigned long long w7 = __ldcs(Wp + (size_t)(m + 7) * S8);
        DO_ROW(w0, m + 0);
        DO_ROW(w1, m + 1);
        DO_ROW(w2, m + 2);
        DO_ROW(w3, m + 3);
        DO_ROW(w4, m + 4);
        DO_ROW(w5, m + 5);
        DO_ROW(w6, m + 6);
        DO_ROW(w7, m + 7);
    }
    #undef DO_ROW

    #pragma unroll
    for (int b = 0; b < B; b++) {
        *reinterpret_cast<unsigned long long*>(
            &g_part[((size_t)s * B + b) * N + n0]) = acc[b];
    }
}

__global__ void __launch_bounds__(256)
snn_reduce(const float* __restrict__ thr,       // [B][N]
           const float* __restrict__ cst,       // [B][N]
           float* __restrict__ out)             // [B][N]
{
    const int idx = blockIdx.x * 256 + threadIdx.x;   // over B*N (65536)

    float sum = 0.f;
    #pragma unroll
    for (int s = 0; s < SPLITS; s++)
        sum += g_part[(size_t)s * B * N + idx];       // 32 independent LDGs

    float o = sum + cst[idx] - thr[idx];
    out[idx] = fminf(fmaxf(o, 0.f), 0.9f);
}

extern "C" void kernel_launch(void* const* d_in, const int* in_sizes, int n_in,
                              void* d_out, int out_size)
{
    const float* pre = (const float*)d_in[0];   // pre_spikes [8,1,8192]
    const float* W   = (const float*)d_in[1];   // W [8192,8192]
    const float* thr = (const float*)d_in[2];   // thr [8,1,8192]
    const float* cst = (const float*)d_in[3];   // const_inp [8,1,8192]
    float* out = (float*)d_out;                 // [8,1,8192]

    dim3 grid(NBLK, SPLITS);                    // 32 x 32 = 1024 blocks
    snn_gemv_split<<<grid, TPB>>>(pre, W);

    snn_reduce<<<(B * N) / 256, 256>>>(thr, cst, out);
}

// round 12
// speedup vs baseline: 1.0457x; 1.0457x over previous
#include <cuda_runtime.h>

#define B 8
#define M 8192
#define N 8192
#define SPLITS 64
#define ROWS (M / SPLITS)            // 128 rows per split
#define TPB 128
#define COLS_PER_BLOCK (TPB * 4)     // 512 columns per block (4 floats per thread)
#define NBLK (N / COLS_PER_BLOCK)    // 16 -> grid 16x64 = 1024 blocks

// Split-K partial sums: [SPLITS][B][N] floats = 16 MB device scratch.
__device__ float g_part[(size_t)SPLITS * B * N];

// Packed fp32x2 FMA: d = a*b + d  (sm_103a FFMA2, only reachable via PTX)
#define FMA2(d, a, b) \
    asm("fma.rn.f32x2 %0, %1, %2, %0;" : "+l"(d) : "l"(a), "l"(b))

__global__ void __launch_bounds__(TPB, 7)
snn_gemv_split(const float* __restrict__ pre,   // [B][M]
               const float* __restrict__ W)     // [M][N] row-major
{
    // Pre-spikes pre-duplicated: pre_s2[r][b] = {p, p} (64-bit), so packed
    // multipliers come straight from LDS.128. 128*8*8 = 8 KB smem.
    __shared__ unsigned long long pre_s2[ROWS][B];

    const int nb  = blockIdx.x;
    const int s   = blockIdx.y;
    const int tid = threadIdx.x;
    const int m0  = s * ROWS;

    // tid == row (ROWS == TPB == 128)
    #pragma unroll
    for (int b = 0; b < B; b++) {
        float p = pre[b * M + m0 + tid];
        float2 pp = make_float2(p, p);
        pre_s2[tid][b] = *reinterpret_cast<unsigned long long*>(&pp);
    }
    __syncthreads();

    const int n0 = nb * COLS_PER_BLOCK + tid * 4;
    const float4* Wp = reinterpret_cast<const float4*>(W + (size_t)m0 * N + n0);
    const size_t S4 = N / 4;         // row stride in float4 (16 B) units

    // acc[b][0] = packed cols {0,1}, acc[b][1] = packed cols {2,3}
    unsigned long long acc[B][2];
    #pragma unroll
    for (int b = 0; b < B; b++) { acc[b][0] = 0ull; acc[b][1] = 0ull; }

    // One row of packed-FMA work; WV is a float4 reinterpreted as 2 packed pairs
    #define DO_ROW(WV, MI) do {                                              \
        ulonglong2 wv = *reinterpret_cast<ulonglong2*>(&(WV));               \
        const ulonglong2* ps =                                               \
            reinterpret_cast<const ulonglong2*>(&pre_s2[(MI)][0]);           \
        ulonglong2 pa = ps[0];  /* batches 0,1 */                            \
        ulonglong2 pb = ps[1];  /* batches 2,3 */                            \
        ulonglong2 pc = ps[2];  /* batches 4,5 */                            \
        ulonglong2 pd = ps[3];  /* batches 6,7 */                            \
        FMA2(acc[0][0], wv.x, pa.x); FMA2(acc[0][1], wv.y, pa.x);            \
        FMA2(acc[1][0], wv.x, pa.y); FMA2(acc[1][1], wv.y, pa.y);            \
        FMA2(acc[2][0], wv.x, pb.x); FMA2(acc[2][1], wv.y, pb.x);            \
        FMA2(acc[3][0], wv.x, pb.y); FMA2(acc[3][1], wv.y, pb.y);            \
        FMA2(acc[4][0], wv.x, pc.x); FMA2(acc[4][1], wv.y, pc.x);            \
        FMA2(acc[5][0], wv.x, pc.y); FMA2(acc[5][1], wv.y, pc.y);            \
        FMA2(acc[6][0], wv.x, pd.x); FMA2(acc[6][1], wv.y, pd.x);            \
        FMA2(acc[7][0], wv.x, pd.y); FMA2(acc[7][1], wv.y, pd.y);            \
    } while (0)

    // Explicit 4-deep load batching, with .CS streaming hint (evict-first in
    // L2) so the one-shot W stream does NOT evict the L2-resident partials.
    #pragma unroll 1
    for (int m = 0; m < ROWS; m += 4) {
        float4 w0 = __ldcs(Wp + (size_t)(m + 0) * S4);
        float4 w1 = __ldcs(Wp + (size_t)(m + 1) * S4);
        float4 w2 = __ldcs(Wp + (size_t)(m + 2) * S4);
        float4 w3 = __ldcs(Wp + (size_t)(m + 3) * S4);
        DO_ROW(w0, m + 0);
        DO_ROW(w1, m + 1);
        DO_ROW(w2, m + 2);
        DO_ROW(w3, m + 3);
    }
    #undef DO_ROW

    #pragma unroll
    for (int b = 0; b < B; b++) {
        float2 lo = *reinterpret_cast<float2*>(&acc[b][0]);
        float2 hi = *reinterpret_cast<float2*>(&acc[b][1]);
        float4 v = make_float4(lo.x, lo.y, hi.x, hi.y);
        *reinterpret_cast<float4*>(&g_part[((size_t)s * B + b) * N + n0]) = v;
    }
}

// Opaque asm load: forces a distinct destination register per load so ptxas
// cannot fuse loads into the FADD chain (which caps MLP at ~8).
#define LDG_F32(dst, ptr) \
    asm volatile("ld.global.f32 %0, [%1];" : "=f"(dst) : "l"(ptr))

__global__ void __launch_bounds__(256)
snn_reduce(const float* __restrict__ thr,       // [B][N]
           const float* __restrict__ cst,       // [B][N]
           float* __restrict__ out)             // [B][N]
{
    const int idx = blockIdx.x * 256 + threadIdx.x;   // over B*N (65536)
    const float* p = &g_part[idx];
    const size_t plane = (size_t)B * N;

    float sum = 0.f;
    #pragma unroll 1
    for (int s = 0; s < SPLITS; s += 16) {
        const float* q = p + (size_t)s * plane;
        float v0, v1, v2, v3, v4, v5, v6, v7;
        float v8, v9, v10, v11, v12, v13, v14, v15;
        LDG_F32(v0,  q + 0 * plane);
        LDG_F32(v1,  q + 1 * plane);
        LDG_F32(v2,  q + 2 * plane);
        LDG_F32(v3,  q + 3 * plane);
        LDG_F32(v4,  q + 4 * plane);
        LDG_F32(v5,  q + 5 * plane);
        LDG_F32(v6,  q + 6 * plane);
        LDG_F32(v7,  q + 7 * plane);
        LDG_F32(v8,  q + 8 * plane);
        LDG_F32(v9,  q + 9 * plane);
        LDG_F32(v10, q + 10 * plane);
        LDG_F32(v11, q + 11 * plane);
        LDG_F32(v12, q + 12 * plane);
        LDG_F32(v13, q + 13 * plane);
        LDG_F32(v14, q + 14 * plane);
        LDG_F32(v15, q + 15 * plane);
        sum += (((v0 + v1) + (v2 + v3)) + ((v4 + v5) + (v6 + v7)))
             + (((v8 + v9) + (v10 + v11)) + ((v12 + v13) + (v14 + v15)));
    }

    float o = sum + cst[idx] - thr[idx];
    out[idx] = fminf(fmaxf(o, 0.f), 0.9f);
}

extern "C" void kernel_launch(void* const* d_in, const int* in_sizes, int n_in,
                              void* d_out, int out_size)
{
    const float* pre = (const float*)d_in[0];   // pre_spikes [8,1,8192]
    const float* W   = (const float*)d_in[1];   // W [8192,8192]
    const float* thr = (const float*)d_in[2];   // thr [8,1,8192]
    const float* cst = (const float*)d_in[3];   // const_inp [8,1,8192]
    float* out = (float*)d_out;                 // [8,1,8192]

    dim3 grid(NBLK, SPLITS);                    // 16 x 64 = 1024 blocks
    snn_gemv_split<<<grid, TPB>>>(pre, W);

    snn_reduce<<<(B * N) / 256, 256>>>(thr, cst, out);
}